// round 16
// baseline (speedup 1.0000x reference)
#include <cuda_runtime.h>
#include <math_constants.h>
#include <cstdint>
#include <cstddef>

// ---------------------------------------------------------------------------
// Problem constants
// ---------------------------------------------------------------------------
namespace cfg {
constexpr int Bb   = 4;
constexpr int Ls   = 2048;
constexpr int Din  = 512;
constexpr int Hh   = 8;
constexpr int Dh   = 64;
constexpr int Dmid = 2048;
constexpr int Mtok = Bb * Ls;   // 8192 tokens
}

// ---------------------------------------------------------------------------
// Scratch (static device globals — no allocations anywhere)
// ---------------------------------------------------------------------------
__device__ float g_Q[cfg::Bb * cfg::Hh * cfg::Ls * cfg::Dh];   // [b,h,l,d] tf32 bits
__device__ float g_K[cfg::Bb * cfg::Hh * cfg::Ls * cfg::Dh];   // tf32 bits
__device__ float g_V[cfg::Bb * cfg::Hh * cfg::Ls * cfg::Dh];   // tf32 bits
__device__ float g_attn[cfg::Mtok * cfg::Din];                 // tf32 bits
__device__ float g_proj[cfg::Mtok * cfg::Din];                 // fp32
__device__ float g_h1[cfg::Mtok * cfg::Din];                   // fp32 (residual)
__device__ float g_h1t[cfg::Mtok * cfg::Din];                  // tf32 bits (FFN1 A)
__device__ float g_mid[cfg::Mtok * cfg::Dmid];                 // tf32 bits
__device__ float g_ff[cfg::Mtok * cfg::Din];                   // fp32

// tf32 inputs; TRANSPOSED tf32 weights (Bt[n][k], K-major, for ldmatrix B)
__device__ float g_qt[cfg::Mtok * cfg::Din];
__device__ float g_kt[cfg::Mtok * cfg::Din];
__device__ float g_vt[cfg::Mtok * cfg::Din];
__device__ float g_WQt[cfg::Din * cfg::Din];
__device__ float g_WKt[cfg::Din * cfg::Din];
__device__ float g_WVt[cfg::Din * cfg::Din];
__device__ float g_WOt[cfg::Din * cfg::Din];
__device__ float g_W1t[cfg::Dmid * cfg::Din];   // [2048][512]
__device__ float g_W2t[cfg::Din * cfg::Dmid];   // [512][2048]

// ---------------------------------------------------------------------------
// PTX helpers
// ---------------------------------------------------------------------------
__device__ __forceinline__ void cpa16(void* smem, const void* gmem) {
    unsigned sa = (unsigned)__cvta_generic_to_shared(smem);
    asm volatile("cp.async.cg.shared.global [%0], [%1], 16;" :: "r"(sa), "l"(gmem));
}
__device__ __forceinline__ void cpa_commit() {
    asm volatile("cp.async.commit_group;");
}
template <int N>
__device__ __forceinline__ void cpa_wait() {
    asm volatile("cp.async.wait_group %0;" :: "n"(N));
}

__device__ __forceinline__ unsigned f2tf(float f) {
    unsigned u;
    asm("cvt.rna.tf32.f32 %0, %1;" : "=r"(u) : "f"(f));
    return u;
}
__device__ __forceinline__ float f2tf_f(float f) { return __uint_as_float(f2tf(f)); }

__device__ __forceinline__ void prefetch_l1(const void* p) {
    asm volatile("prefetch.global.L1 [%0];" :: "l"(p));
}

// mma.m16n8k8 tf32: A 4 regs, B 2 regs, C/D 4 floats (in-place accumulate)
__device__ __forceinline__ void mma_tf32_16n8k8(float d[4], const unsigned a[4],
                                                const unsigned b[2]) {
    asm volatile(
        "mma.sync.aligned.m16n8k8.row.col.f32.tf32.tf32.f32 "
        "{%0,%1,%2,%3}, {%4,%5,%6,%7}, {%8,%9}, {%0,%1,%2,%3};"
        : "+f"(d[0]), "+f"(d[1]), "+f"(d[2]), "+f"(d[3])
        : "r"(a[0]), "r"(a[1]), "r"(a[2]), "r"(a[3]), "r"(b[0]), "r"(b[1]));
}

// ldmatrix: lane L receives word (L%4) of row (L/4) of each 8x8 b16 matrix.
// For 32-bit tf32, each "word" is one element -> exactly the mma fragment map.
__device__ __forceinline__ void ldsm_x4(unsigned r[4], unsigned addr) {
    asm volatile("ldmatrix.sync.aligned.m8n8.x4.shared.b16 {%0,%1,%2,%3}, [%4];"
        : "=r"(r[0]), "=r"(r[1]), "=r"(r[2]), "=r"(r[3]) : "r"(addr));
}
__device__ __forceinline__ void ldsm_x2(unsigned r[2], unsigned addr) {
    asm volatile("ldmatrix.sync.aligned.m8n8.x2.shared.b16 {%0,%1}, [%2];"
        : "=r"(r[0]), "=r"(r[1]) : "r"(addr));
}

// ---------------------------------------------------------------------------
// Prologue: tf32 cvt for q/k/v; batched tiled transpose+cvt for all 6 weights.
// ---------------------------------------------------------------------------
struct Cvt3 { const float* s[3]; float* d[3]; int n[3]; };

__global__ __launch_bounds__(256) void cvt3_kernel(Cvt3 a)
{
    const int tid = blockIdx.x * 256 + threadIdx.x;
    const int stride = gridDim.x * 256;
#pragma unroll
    for (int seg = 0; seg < 3; seg++) {
        const float4* src = (const float4*)a.s[seg];
        float4*       dst = (float4*)a.d[seg];
        const int n4 = a.n[seg] >> 2;
        for (int i = tid; i < n4; i += stride) {
            float4 v = src[i];
            v.x = f2tf_f(v.x); v.y = f2tf_f(v.y);
            v.z = f2tf_f(v.z); v.w = f2tf_f(v.w);
            dst[i] = v;
        }
    }
}

// Batched Wt[n][k] = tf32(W[k][n]) for 6 weight matrices in ONE launch.
// Each 32x32 tile is one block; tstart[] gives the cumulative tile offsets.
struct T6 {
    const float* W[6];
    float*       Wt[6];
    int          K[6], N[6];
    int          tstart[7];
};

__global__ __launch_bounds__(256) void transpose6_kernel(T6 j)
{
    __shared__ float t[32][33];
    const int tile = blockIdx.x;
    int job = 0;
#pragma unroll
    for (int i = 0; i < 6; i++)
        if (tile >= j.tstart[i + 1]) job = i + 1;

    const float* W  = j.W[job];
    float*       Wt = j.Wt[job];
    const int K = j.K[job], N = j.N[job];
    const int local = tile - j.tstart[job];
    const int ntx = N >> 5;
    const int n0 = (local % ntx) * 32;
    const int k0 = (local / ntx) * 32;

    const int tx = threadIdx.x & 31, ty = (threadIdx.x >> 5) * 4;
#pragma unroll
    for (int i = 0; i < 4; i++)
        t[ty + i][tx] = f2tf_f(W[(size_t)(k0 + ty + i) * N + n0 + tx]);
    __syncthreads();
#pragma unroll
    for (int i = 0; i < 4; i++)
        Wt[(size_t)(n0 + ty + i) * K + k0 + tx] = t[tx][ty + i];
}

// ---------------------------------------------------------------------------
// Raw-mma tf32 GEMM with LDSM operand path (unchanged from R15 — proven).
// C[M,N] = A[M,K] * Bt[N,K]^T, fp32 accum, operands pre-truncated tf32 bits.
// Block tile 128x128x32, 256 threads (8 warps, 2x4), warp tile 64x32.
// 3-stage cp.async, 1 barrier/iter, 2 CTAs/SM.
// Epilogues: 0 plain fp32, 2 head-split [b,h,l,64]+tf32, 3 relu+tf32.
// ---------------------------------------------------------------------------
constexpr int BM = 128, BN = 128, BK = 32;
constexpr int ALD = BK + 4;        // 36
constexpr int BLD = BK + 4;        // 36 (B tile is [n][k])
constexpr int AS_F = BM * ALD;     // 4608 floats / stage
constexpr int BS_F = BN * BLD;     // 4608 floats / stage
constexpr int GST  = 3;
constexpr size_t GEMM_SMEM = (size_t)GST * (AS_F + BS_F) * sizeof(float);  // 110,592 B

template <int EPI>
__device__ __forceinline__ void gemm_dev(
    const float* __restrict__ A, const float* __restrict__ Bt,
    float* __restrict__ C, int M, int N, int K)
{
    extern __shared__ float gsm[];
    float* As = gsm;
    float* Bs = gsm + GST * AS_F;

    const int tid  = threadIdx.x;
    const int bm   = blockIdx.y * BM;
    const int bn   = blockIdx.x * BN;
    const int warp = tid >> 5;
    const int lane = tid & 31;
    const int g    = lane >> 2;    // 0..7
    const int q    = lane & 3;     // 0..3
    const int wr   = warp >> 2;    // 0..1
    const int wc   = warp & 3;     // 0..3

    float acc[4][4][4];
#pragma unroll
    for (int mi = 0; mi < 4; mi++)
#pragma unroll
        for (int ni = 0; ni < 4; ni++)
#pragma unroll
            for (int e = 0; e < 4; e++) acc[mi][ni][e] = 0.0f;

    auto load_tiles = [&](int buf, int kt) {
        const int k0 = kt * BK;
        float* Ab = As + buf * AS_F;
        float* Bb = Bs + buf * BS_F;
#pragma unroll
        for (int i = 0; i < 4; i++) {
            int lin = tid + i * 256;
            int r   = lin >> 3;
            int c4  = (lin & 7) * 4;
            cpa16(Ab + r * ALD + c4, A + (size_t)(bm + r) * K + k0 + c4);
        }
#pragma unroll
        for (int i = 0; i < 4; i++) {
            int lin = tid + i * 256;
            int r   = lin >> 3;
            int c4  = (lin & 7) * 4;
            cpa16(Bb + r * BLD + c4, Bt + (size_t)(bn + r) * K + k0 + c4);
        }
        cpa_commit();
    };

    const int nkt = K / BK;
    load_tiles(0, 0);
    load_tiles(1, 1);

    const int lrow = lane & 7;
    const int lbit = (lane >> 3) & 1;
    const int lco4 = (lane >> 4) * 4;
    const unsigned sA0 = (unsigned)__cvta_generic_to_shared(As);
    const unsigned sB0 = (unsigned)__cvta_generic_to_shared(Bs);
    const unsigned aoff = ((wr * 64 + lbit * 8 + lrow) * ALD + lco4) * 4;
    const unsigned boff = ((wc * 32 + lrow) * BLD + lbit * 4) * 4;

    for (int kt = 0; kt < nkt; kt++) {
        if (kt + 1 < nkt) cpa_wait<1>(); else cpa_wait<0>();
        __syncthreads();
        if (kt + 2 < nkt) load_tiles((kt + 2) % GST, kt + 2);

        const int buf = kt % GST;
        const unsigned abase = sA0 + buf * (AS_F * 4) + aoff;
        const unsigned bbase = sB0 + buf * (BS_F * 4) + boff;

#pragma unroll
        for (int j = 0; j < 4; j++) {
            unsigned bfr[4][2];
#pragma unroll
            for (int ni = 0; ni < 4; ni++)
                ldsm_x2(bfr[ni], bbase + (unsigned)(ni * 8 * BLD * 4 + j * 32));
#pragma unroll
            for (int mi = 0; mi < 4; mi++) {
                unsigned a[4];
                ldsm_x4(a, abase + (unsigned)(mi * 16 * ALD * 4 + j * 32));
#pragma unroll
                for (int ni = 0; ni < 4; ni++)
                    mma_tf32_16n8k8(acc[mi][ni], a, bfr[ni]);
            }
        }
    }

#pragma unroll
    for (int mi = 0; mi < 4; mi++) {
        const int gr0 = bm + wr * 64 + mi * 16 + g;
        const int gr1 = gr0 + 8;
#pragma unroll
        for (int ni = 0; ni < 4; ni++) {
            const int gc = bn + wc * 32 + ni * 8 + 2 * q;
            float d0 = acc[mi][ni][0], d1 = acc[mi][ni][1];
            float d2 = acc[mi][ni][2], d3 = acc[mi][ni][3];
            if (EPI == 3) {
                d0 = fmaxf(d0, 0.0f); d1 = fmaxf(d1, 0.0f);
                d2 = fmaxf(d2, 0.0f); d3 = fmaxf(d3, 0.0f);
            }
            if (EPI == 2) {
                int h = gc >> 6, d = gc & 63;
                int b0 = gr0 >> 11, l0i = gr0 & (cfg::Ls - 1);
                int b1 = gr1 >> 11, l1i = gr1 & (cfg::Ls - 1);
                float2 w0 = { f2tf_f(d0), f2tf_f(d1) };
                float2 w1 = { f2tf_f(d2), f2tf_f(d3) };
                *(float2*)&C[(((size_t)(b0 * cfg::Hh + h) * cfg::Ls + l0i) << 6) + d] = w0;
                *(float2*)&C[(((size_t)(b1 * cfg::Hh + h) * cfg::Ls + l1i) << 6) + d] = w1;
            } else if (EPI == 3) {
                float2 w0 = { f2tf_f(d0), f2tf_f(d1) };
                float2 w1 = { f2tf_f(d2), f2tf_f(d3) };
                *(float2*)&C[(size_t)gr0 * N + gc] = w0;
                *(float2*)&C[(size_t)gr1 * N + gc] = w1;
            } else {
                float2 w0 = { d0, d1 };
                float2 w1 = { d2, d3 };
                *(float2*)&C[(size_t)gr0 * N + gc] = w0;
                *(float2*)&C[(size_t)gr1 * N + gc] = w1;
            }
        }
    }
}

template <int EPI>
__global__ __launch_bounds__(256, 2) void gemm_tf32(
    const float* __restrict__ A, const float* __restrict__ Bt,
    float* __restrict__ C, int M, int N, int K)
{
    gemm_dev<EPI>(A, Bt, C, M, N, K);
}

__global__ __launch_bounds__(256, 2) void gemm_qkv(
    const float* __restrict__ q, const float* __restrict__ k,
    const float* __restrict__ v,
    const float* __restrict__ WQ, const float* __restrict__ WK,
    const float* __restrict__ WV,
    float* __restrict__ Qd, float* __restrict__ Kd, float* __restrict__ Vd)
{
    const int z = blockIdx.z;
    const float* A = (z == 0) ? q : (z == 1) ? k : v;
    const float* W = (z == 0) ? WQ : (z == 1) ? WK : WV;
    float* C       = (z == 0) ? Qd : (z == 1) ? Kd : Vd;
    gemm_dev<2>(A, W, C, cfg::Mtok, cfg::Din, cfg::Din);
}

// ---------------------------------------------------------------------------
// Flash attention: register-resident S/O, m16n8k8 tf32.
// NEW: mask rows are L1-prefetched right after the barrier; the S=QK^T mma
// loop (~1-2k cyc) covers the gmem latency, so the actual mask loads hit L1.
// ---------------------------------------------------------------------------
constexpr int FQ2  = 128;
constexpr int QSTR = 68;
constexpr int KSTR = 68;
constexpr int VSTR = 72;

constexpr int SM_Q = 0;
constexpr int SM_K = SM_Q + FQ2 * QSTR;
constexpr int SM_V = SM_K + 2 * 64 * KSTR;
constexpr int FLASH2_FLOATS = SM_V + 2 * 64 * VSTR;
constexpr size_t FLASH2_SMEM = (size_t)FLASH2_FLOATS * sizeof(float);  // 106,496 B

__global__ __launch_bounds__(256, 2) void flash2_kernel(
    const float* __restrict__ Qg, const float* __restrict__ Kg,
    const float* __restrict__ Vg, const float* __restrict__ maskg,
    float* __restrict__ Og)
{
    extern __shared__ float sm[];
    float* Qs = sm + SM_Q;
    float* Ks = sm + SM_K;
    float* Vs = sm + SM_V;

    const int tid  = threadIdx.x;
    const int warp = tid >> 5;
    const int lane = tid & 31;
    const int g    = lane >> 2;
    const int q    = lane & 3;
    const int b    = blockIdx.z;
    const int h    = blockIdx.y;
    const int q0   = blockIdx.x * FQ2;
    const int wrow = warp * 16;

    const size_t bh = (size_t)(b * cfg::Hh + h) * cfg::Ls;
    const float* Qbase = Qg + (bh + q0) * cfg::Dh;

#pragma unroll
    for (int i = 0; i < 8; i++) {
        int lin = tid + i * 256;
        int r = lin >> 4, c4 = (lin & 15) * 4;
        cpa16(&Qs[r * QSTR + c4], Qbase + r * cfg::Dh + c4);
    }

    auto loadKV = [&](int buf, int kt) {
        const float* Kb = Kg + (bh + kt * 64) * cfg::Dh;
        const float* Vb = Vg + (bh + kt * 64) * cfg::Dh;
#pragma unroll
        for (int i = 0; i < 4; i++) {
            int lin = tid + i * 256;
            int r = lin >> 4, c4 = (lin & 15) * 4;
            cpa16(&Ks[buf * 64 * KSTR + r * KSTR + c4], Kb + r * cfg::Dh + c4);
            cpa16(&Vs[buf * 64 * VSTR + r * VSTR + c4], Vb + r * cfg::Dh + c4);
        }
    };
    loadKV(0, 0);
    cpa_commit();

    float m0 = -CUDART_INF_F, m1 = -CUDART_INF_F;
    float l0 = 0.0f, l1 = 0.0f;
    float o[8][4];
#pragma unroll
    for (int t = 0; t < 8; t++)
#pragma unroll
        for (int e = 0; e < 4; e++) o[t][e] = 0.0f;

    const float* mrow0 = maskg + ((size_t)b * cfg::Ls + q0 + wrow + g) * cfg::Ls;
    const float* mrow1 = mrow0 + 8 * (size_t)cfg::Ls;

    const unsigned* Qu = (const unsigned*)Qs;
    const int srcA = (lane & 28) | (q >> 1);
    const int srcB = srcA + 2;
    const bool odd = (q & 1) != 0;

    for (int kt = 0; kt < cfg::Ls / 64; kt++) {
        const int cur = kt & 1;
        cpa_wait<0>();
        __syncthreads();
        if (kt + 1 < cfg::Ls / 64) { loadKV(cur ^ 1, kt + 1); cpa_commit(); }

        const int kcol = kt * 64;
        // ---- L1-prefetch this iter's mask rows (consumed after the S loop) ----
#pragma unroll
        for (int t = 0; t < 8; t++) {
            prefetch_l1(mrow0 + kcol + t * 8 + 2 * q);
            prefetch_l1(mrow1 + kcol + t * 8 + 2 * q);
        }

        const unsigned* Ku = (const unsigned*)(Ks + cur * 64 * KSTR);
        const unsigned* Vu = (const unsigned*)(Vs + cur * 64 * VSTR);

        float s[8][4];
#pragma unroll
        for (int t = 0; t < 8; t++)
#pragma unroll
            for (int e = 0; e < 4; e++) s[t][e] = 0.0f;

#pragma unroll
        for (int j = 0; j < 8; j++) {
            unsigned a[4];
            a[0] = Qu[(wrow + g) * QSTR + j * 8 + q];
            a[1] = Qu[(wrow + g + 8) * QSTR + j * 8 + q];
            a[2] = Qu[(wrow + g) * QSTR + j * 8 + q + 4];
            a[3] = Qu[(wrow + g + 8) * QSTR + j * 8 + q + 4];
#pragma unroll
            for (int t = 0; t < 8; t++) {
                unsigned bf[2];
                bf[0] = Ku[(t * 8 + g) * KSTR + j * 8 + q];
                bf[1] = Ku[(t * 8 + g) * KSTR + j * 8 + q + 4];
                mma_tf32_16n8k8(s[t], a, bf);
            }
        }

#pragma unroll
        for (int t = 0; t < 8; t++) {
            float2 mk0 = *(const float2*)(mrow0 + kcol + t * 8 + 2 * q);
            float2 mk1 = *(const float2*)(mrow1 + kcol + t * 8 + 2 * q);
            s[t][0] = s[t][0] * 0.125f + mk0.x;
            s[t][1] = s[t][1] * 0.125f + mk0.y;
            s[t][2] = s[t][2] * 0.125f + mk1.x;
            s[t][3] = s[t][3] * 0.125f + mk1.y;
        }

        float mx0 = -CUDART_INF_F, mx1 = -CUDART_INF_F;
#pragma unroll
        for (int t = 0; t < 8; t++) {
            mx0 = fmaxf(mx0, fmaxf(s[t][0], s[t][1]));
            mx1 = fmaxf(mx1, fmaxf(s[t][2], s[t][3]));
        }
        mx0 = fmaxf(mx0, __shfl_xor_sync(0xffffffffu, mx0, 1));
        mx0 = fmaxf(mx0, __shfl_xor_sync(0xffffffffu, mx0, 2));
        mx1 = fmaxf(mx1, __shfl_xor_sync(0xffffffffu, mx1, 1));
        mx1 = fmaxf(mx1, __shfl_xor_sync(0xffffffffu, mx1, 2));

        const float m0n = fmaxf(m0, mx0);
        const float m1n = fmaxf(m1, mx1);
        const float c0  = __expf(m0 - m0n);
        const float c1  = __expf(m1 - m1n);

        float sum0 = 0.0f, sum1 = 0.0f;
#pragma unroll
        for (int t = 0; t < 8; t++) {
            s[t][0] = __expf(s[t][0] - m0n);
            s[t][1] = __expf(s[t][1] - m0n);
            s[t][2] = __expf(s[t][2] - m1n);
            s[t][3] = __expf(s[t][3] - m1n);
            sum0 += s[t][0] + s[t][1];
            sum1 += s[t][2] + s[t][3];
        }
        sum0 += __shfl_xor_sync(0xffffffffu, sum0, 1);
        sum0 += __shfl_xor_sync(0xffffffffu, sum0, 2);
        sum1 += __shfl_xor_sync(0xffffffffu, sum1, 1);
        sum1 += __shfl_xor_sync(0xffffffffu, sum1, 2);

        l0 = l0 * c0 + sum0;
        l1 = l1 * c1 + sum1;
        m0 = m0n;
        m1 = m1n;

#pragma unroll
        for (int t = 0; t < 8; t++) {
            o[t][0] *= c0; o[t][1] *= c0;
            o[t][2] *= c1; o[t][3] *= c1;
        }

#pragma unroll
        for (int j = 0; j < 8; j++) {
            float u0 = __shfl_sync(0xffffffffu, s[j][0], srcA);
            float u1 = __shfl_sync(0xffffffffu, s[j][1], srcA);
            float v0 = __shfl_sync(0xffffffffu, s[j][0], srcB);
            float v1 = __shfl_sync(0xffffffffu, s[j][1], srcB);
            float w0 = __shfl_sync(0xffffffffu, s[j][2], srcA);
            float w1 = __shfl_sync(0xffffffffu, s[j][3], srcA);
            float x0 = __shfl_sync(0xffffffffu, s[j][2], srcB);
            float x1 = __shfl_sync(0xffffffffu, s[j][3], srcB);
            unsigned a[4];
            a[0] = f2tf(odd ? u1 : u0);
            a[1] = f2tf(odd ? w1 : w0);
            a[2] = f2tf(odd ? v1 : v0);
            a[3] = f2tf(odd ? x1 : x0);
#pragma unroll
            for (int t = 0; t < 8; t++) {
                unsigned bf[2];
                bf[0] = Vu[(j * 8 + q) * VSTR + t * 8 + g];
                bf[1] = Vu[(j * 8 + q + 4) * VSTR + t * 8 + g];
                mma_tf32_16n8k8(o[t], a, bf);
            }
        }
    }

    const float inv0 = 1.0f / l0;
    const float inv1 = 1.0f / l1;
    float* orow0 = Og + ((size_t)b * cfg::Ls + q0 + wrow + g) * cfg::Din + h * cfg::Dh;
    float* orow1 = orow0 + 8 * (size_t)cfg::Din;
#pragma unroll
    for (int t = 0; t < 8; t++) {
        float2 w0 = { f2tf_f(o[t][0] * inv0), f2tf_f(o[t][1] * inv0) };
        float2 w1 = { f2tf_f(o[t][2] * inv1), f2tf_f(o[t][3] * inv1) };
        *(float2*)&orow0[t * 8 + 2 * q] = w0;
        *(float2*)&orow1[t * 8 + 2 * q] = w1;
    }
}

// ---------------------------------------------------------------------------
// Fused residual-add + LayerNorm over last dim (512). One block per row.
// ---------------------------------------------------------------------------
template <bool T32>
__global__ __launch_bounds__(128) void ln_add_kernel(
    const float* __restrict__ x, const float* __restrict__ y,
    float* __restrict__ out, float* __restrict__ out_t)
{
    const int row = blockIdx.x;
    const float* px = x + (size_t)row * cfg::Din;
    const float* py = y + (size_t)row * cfg::Din;

    float v[4];
    float s = 0.0f, sq = 0.0f;
#pragma unroll
    for (int i = 0; i < 4; i++) {
        int c = threadIdx.x + i * 128;
        v[i] = px[c] + py[c];
        s  += v[i];
        sq += v[i] * v[i];
    }
#pragma unroll
    for (int o = 16; o > 0; o >>= 1) {
        s  += __shfl_xor_sync(0xffffffffu, s, o);
        sq += __shfl_xor_sync(0xffffffffu, sq, o);
    }
    __shared__ float ws[4], wq[4];
    __shared__ float mean_s, inv_s;
    const int warp = threadIdx.x >> 5, lane = threadIdx.x & 31;
    if (lane == 0) { ws[warp] = s; wq[warp] = sq; }
    __syncthreads();
    if (threadIdx.x == 0) {
        float S = ws[0] + ws[1] + ws[2] + ws[3];
        float Q = wq[0] + wq[1] + wq[2] + wq[3];
        float mean = S * (1.0f / cfg::Din);
        float var  = Q * (1.0f / cfg::Din) - mean * mean;
        mean_s = mean;
        inv_s  = rsqrtf(var + 1e-5f);
    }
    __syncthreads();
    float* po = out + (size_t)row * cfg::Din;
    float* pt = out_t + (size_t)row * cfg::Din;
#pragma unroll
    for (int i = 0; i < 4; i++) {
        int c = threadIdx.x + i * 128;
        float r = (v[i] - mean_s) * inv_s;
        po[c] = r;
        if (T32) pt[c] = f2tf_f(r);
    }
}

// ---------------------------------------------------------------------------
// kernel_launch
// ---------------------------------------------------------------------------
extern "C" void kernel_launch(void* const* d_in, const int* in_sizes, int n_in,
                              void* d_out, int out_size)
{
    const float* query = (const float*)d_in[0];
    const float* key   = (const float*)d_in[1];
    const float* value = (const float*)d_in[2];
    const float* mask  = (const float*)d_in[3];
    const float* WQ    = (const float*)d_in[4];
    const float* WK    = (const float*)d_in[5];
    const float* WV    = (const float*)d_in[6];
    const float* WO    = (const float*)d_in[7];
    const float* W1    = (const float*)d_in[8];
    const float* W2    = (const float*)d_in[9];
    float* out = (float*)d_out;

    float *Qd, *Kd, *Vd, *attn, *proj, *h1, *h1t, *mid, *ff;
    float *qt, *kt, *vt, *WQt, *WKt, *WVt, *WOt, *W1t, *W2t;
    cudaGetSymbolAddress((void**)&Qd,   g_Q);
    cudaGetSymbolAddress((void**)&Kd,   g_K);
    cudaGetSymbolAddress((void**)&Vd,   g_V);
    cudaGetSymbolAddress((void**)&attn, g_attn);
    cudaGetSymbolAddress((void**)&proj, g_proj);
    cudaGetSymbolAddress((void**)&h1,   g_h1);
    cudaGetSymbolAddress((void**)&h1t,  g_h1t);
    cudaGetSymbolAddress((void**)&mid,  g_mid);
    cudaGetSymbolAddress((void**)&ff,   g_ff);
    cudaGetSymbolAddress((void**)&qt,   g_qt);
    cudaGetSymbolAddress((void**)&kt,   g_kt);
    cudaGetSymbolAddress((void**)&vt,   g_vt);
    cudaGetSymbolAddress((void**)&WQt,  g_WQt);
    cudaGetSymbolAddress((void**)&WKt,  g_WKt);
    cudaGetSymbolAddress((void**)&WVt,  g_WVt);
    cudaGetSymbolAddress((void**)&WOt,  g_WOt);
    cudaGetSymbolAddress((void**)&W1t,  g_W1t);
    cudaGetSymbolAddress((void**)&W2t,  g_W2t);

    cudaFuncSetAttribute(flash2_kernel, cudaFuncAttributeMaxDynamicSharedMemorySize,
                         (int)FLASH2_SMEM);
    cudaFuncSetAttribute(gemm_tf32<0>, cudaFuncAttributeMaxDynamicSharedMemorySize,
                         (int)GEMM_SMEM);
    cudaFuncSetAttribute(gemm_tf32<3>, cudaFuncAttributeMaxDynamicSharedMemorySize,
                         (int)GEMM_SMEM);
    cudaFuncSetAttribute(gemm_qkv, cudaFuncAttributeMaxDynamicSharedMemorySize,
                         (int)GEMM_SMEM);

    // -- prologue: tf32 cvt of q/k/v + ONE batched transpose+cvt launch --
    const int nIn = cfg::Mtok * cfg::Din;
    Cvt3 cv;
    cv.s[0] = query; cv.d[0] = qt; cv.n[0] = nIn;
    cv.s[1] = key;   cv.d[1] = kt; cv.n[1] = nIn;
    cv.s[2] = value; cv.d[2] = vt; cv.n[2] = nIn;
    cvt3_kernel<<<1024, 256>>>(cv);

    T6 tj;
    const float* Ws[6] = { WQ, WK, WV, WO, W1, W2 };
    float* Wts[6]      = { WQt, WKt, WVt, WOt, W1t, W2t };
    const int Ks[6]    = { 512, 512, 512, 512, 512, 2048 };
    const int Ns[6]    = { 512, 512, 512, 512, 2048, 512 };
    int acc_t = 0;
    for (int i = 0; i < 6; i++) {
        tj.W[i] = Ws[i]; tj.Wt[i] = Wts[i]; tj.K[i] = Ks[i]; tj.N[i] = Ns[i];
        tj.tstart[i] = acc_t;
        acc_t += (Ks[i] / 32) * (Ns[i] / 32);
    }
    tj.tstart[6] = acc_t;                       // 3072
    transpose6_kernel<<<acc_t, 256>>>(tj);

    const dim3 gProj(cfg::Din / BN, cfg::Mtok / BM);        // (4, 64)
    const dim3 gQkv (cfg::Din / BN, cfg::Mtok / BM, 3);     // (4, 64, 3)
    const dim3 gFfn1(cfg::Dmid / BN, cfg::Mtok / BM);       // (16, 64)

    // Fused QKV projections (head-split + tf32 epilogue)
    gemm_qkv<<<gQkv, 256, GEMM_SMEM>>>(qt, kt, vt, WQt, WKt, WVt, Qd, Kd, Vd);

    // Flash attention (consumes tf32 Q/K/V, emits tf32 attn)
    dim3 gFlash(cfg::Ls / FQ2, cfg::Hh, cfg::Bb);           // (16, 8, 4)
    flash2_kernel<<<gFlash, 256, FLASH2_SMEM>>>(Qd, Kd, Vd, mask, attn);

    // Output projection + residual LN (fp32 out + tf32 copy for FFN1)
    gemm_tf32<0><<<gProj, 256, GEMM_SMEM>>>(attn, WOt, proj, cfg::Mtok, cfg::Din, cfg::Din);
    ln_add_kernel<true><<<cfg::Mtok, 128>>>(query, proj, h1, h1t);

    // FFN (FFN1: relu + tf32 epilogue; FFN2: fp32)
    gemm_tf32<3><<<gFfn1, 256, GEMM_SMEM>>>(h1t, W1t, mid, cfg::Mtok, cfg::Dmid, cfg::Din);
    gemm_tf32<0><<<gProj, 256, GEMM_SMEM>>>(mid, W2t, ff, cfg::Mtok, cfg::Din, cfg::Dmid);
    ln_add_kernel<false><<<cfg::Mtok, 128>>>(h1, ff, out, out);

    (void)in_sizes; (void)n_in; (void)out_size;
}

// round 17
// speedup vs baseline: 1.1099x; 1.1099x over previous
#include <cuda_runtime.h>
#include <math_constants.h>
#include <cstdint>
#include <cstddef>

// ---------------------------------------------------------------------------
// Problem constants
// ---------------------------------------------------------------------------
namespace cfg {
constexpr int Bb   = 4;
constexpr int Ls   = 2048;
constexpr int Din  = 512;
constexpr int Hh   = 8;
constexpr int Dh   = 64;
constexpr int Dmid = 2048;
constexpr int Mtok = Bb * Ls;   // 8192 tokens
}

// ---------------------------------------------------------------------------
// Scratch (static device globals — no allocations anywhere)
// ---------------------------------------------------------------------------
__device__ float g_Q[cfg::Bb * cfg::Hh * cfg::Ls * cfg::Dh];   // [b,h,l,d] tf32 bits
__device__ float g_K[cfg::Bb * cfg::Hh * cfg::Ls * cfg::Dh];   // tf32 bits
__device__ float g_V[cfg::Bb * cfg::Hh * cfg::Ls * cfg::Dh];   // tf32 bits
__device__ float g_attn[cfg::Mtok * cfg::Din];                 // tf32 bits
__device__ float g_proj[cfg::Mtok * cfg::Din];                 // fp32
__device__ float g_h1[cfg::Mtok * cfg::Din];                   // fp32 (residual)
__device__ float g_h1t[cfg::Mtok * cfg::Din];                  // tf32 bits (FFN1 A)
__device__ float g_mid[cfg::Mtok * cfg::Dmid];                 // tf32 bits
__device__ float g_ff[cfg::Mtok * cfg::Din];                   // fp32

// tf32 inputs; TRANSPOSED tf32 weights (Bt[n][k], K-major, for ldmatrix B)
__device__ float g_qt[cfg::Mtok * cfg::Din];
__device__ float g_kt[cfg::Mtok * cfg::Din];
__device__ float g_vt[cfg::Mtok * cfg::Din];
__device__ float g_WQt[cfg::Din * cfg::Din];
__device__ float g_WKt[cfg::Din * cfg::Din];
__device__ float g_WVt[cfg::Din * cfg::Din];
__device__ float g_WOt[cfg::Din * cfg::Din];
__device__ float g_W1t[cfg::Dmid * cfg::Din];   // [2048][512]
__device__ float g_W2t[cfg::Din * cfg::Dmid];   // [512][2048]

// ---------------------------------------------------------------------------
// PTX helpers
// ---------------------------------------------------------------------------
__device__ __forceinline__ void cpa16(void* smem, const void* gmem) {
    unsigned sa = (unsigned)__cvta_generic_to_shared(smem);
    asm volatile("cp.async.cg.shared.global [%0], [%1], 16;" :: "r"(sa), "l"(gmem));
}
__device__ __forceinline__ void cpa_commit() {
    asm volatile("cp.async.commit_group;");
}
template <int N>
__device__ __forceinline__ void cpa_wait() {
    asm volatile("cp.async.wait_group %0;" :: "n"(N));
}

__device__ __forceinline__ unsigned f2tf(float f) {
    unsigned u;
    asm("cvt.rna.tf32.f32 %0, %1;" : "=r"(u) : "f"(f));
    return u;
}
__device__ __forceinline__ float f2tf_f(float f) { return __uint_as_float(f2tf(f)); }

// mma.m16n8k8 tf32: A 4 regs, B 2 regs, C/D 4 floats (in-place accumulate)
__device__ __forceinline__ void mma_tf32_16n8k8(float d[4], const unsigned a[4],
                                                const unsigned b[2]) {
    asm volatile(
        "mma.sync.aligned.m16n8k8.row.col.f32.tf32.tf32.f32 "
        "{%0,%1,%2,%3}, {%4,%5,%6,%7}, {%8,%9}, {%0,%1,%2,%3};"
        : "+f"(d[0]), "+f"(d[1]), "+f"(d[2]), "+f"(d[3])
        : "r"(a[0]), "r"(a[1]), "r"(a[2]), "r"(a[3]), "r"(b[0]), "r"(b[1]));
}

// ldmatrix (tf32: each "word" = one 32-bit element; mapping = mma fragment map)
__device__ __forceinline__ void ldsm_x4(unsigned r[4], unsigned addr) {
    asm volatile("ldmatrix.sync.aligned.m8n8.x4.shared.b16 {%0,%1,%2,%3}, [%4];"
        : "=r"(r[0]), "=r"(r[1]), "=r"(r[2]), "=r"(r[3]) : "r"(addr));
}
__device__ __forceinline__ void ldsm_x2(unsigned r[2], unsigned addr) {
    asm volatile("ldmatrix.sync.aligned.m8n8.x2.shared.b16 {%0,%1}, [%2];"
        : "=r"(r[0]), "=r"(r[1]) : "r"(addr));
}

// ---------------------------------------------------------------------------
// Prologue: tf32 cvt for q/k/v; batched tiled transpose+cvt for all 6 weights.
// ---------------------------------------------------------------------------
struct Cvt3 { const float* s[3]; float* d[3]; int n[3]; };

__global__ __launch_bounds__(256) void cvt3_kernel(Cvt3 a)
{
    const int tid = blockIdx.x * 256 + threadIdx.x;
    const int stride = gridDim.x * 256;
#pragma unroll
    for (int seg = 0; seg < 3; seg++) {
        const float4* src = (const float4*)a.s[seg];
        float4*       dst = (float4*)a.d[seg];
        const int n4 = a.n[seg] >> 2;
        for (int i = tid; i < n4; i += stride) {
            float4 v = src[i];
            v.x = f2tf_f(v.x); v.y = f2tf_f(v.y);
            v.z = f2tf_f(v.z); v.w = f2tf_f(v.w);
            dst[i] = v;
        }
    }
}

// Batched Wt[n][k] = tf32(W[k][n]) for 6 weight matrices in ONE launch.
struct T6 {
    const float* W[6];
    float*       Wt[6];
    int          K[6], N[6];
    int          tstart[7];
};

__global__ __launch_bounds__(256) void transpose6_kernel(T6 j)
{
    __shared__ float t[32][33];
    const int tile = blockIdx.x;
    int job = 0;
#pragma unroll
    for (int i = 0; i < 6; i++)
        if (tile >= j.tstart[i + 1]) job = i + 1;

    const float* W  = j.W[job];
    float*       Wt = j.Wt[job];
    const int K = j.K[job], N = j.N[job];
    const int local = tile - j.tstart[job];
    const int ntx = N >> 5;
    const int n0 = (local % ntx) * 32;
    const int k0 = (local / ntx) * 32;

    const int tx = threadIdx.x & 31, ty = (threadIdx.x >> 5) * 4;
#pragma unroll
    for (int i = 0; i < 4; i++)
        t[ty + i][tx] = f2tf_f(W[(size_t)(k0 + ty + i) * N + n0 + tx]);
    __syncthreads();
#pragma unroll
    for (int i = 0; i < 4; i++)
        Wt[(size_t)(n0 + ty + i) * K + k0 + tx] = t[tx][ty + i];
}

// ---------------------------------------------------------------------------
// Raw-mma tf32 GEMM with LDSM operand path (unchanged — proven at 727).
// ---------------------------------------------------------------------------
constexpr int BM = 128, BN = 128, BK = 32;
constexpr int ALD = BK + 4;        // 36
constexpr int BLD = BK + 4;        // 36 (B tile is [n][k])
constexpr int AS_F = BM * ALD;
constexpr int BS_F = BN * BLD;
constexpr int GST  = 3;
constexpr size_t GEMM_SMEM = (size_t)GST * (AS_F + BS_F) * sizeof(float);  // 110,592 B

template <int EPI>
__device__ __forceinline__ void gemm_dev(
    const float* __restrict__ A, const float* __restrict__ Bt,
    float* __restrict__ C, int M, int N, int K)
{
    extern __shared__ float gsm[];
    float* As = gsm;
    float* Bs = gsm + GST * AS_F;

    const int tid  = threadIdx.x;
    const int bm   = blockIdx.y * BM;
    const int bn   = blockIdx.x * BN;
    const int warp = tid >> 5;
    const int lane = tid & 31;
    const int g    = lane >> 2;
    const int q    = lane & 3;
    const int wr   = warp >> 2;
    const int wc   = warp & 3;

    float acc[4][4][4];
#pragma unroll
    for (int mi = 0; mi < 4; mi++)
#pragma unroll
        for (int ni = 0; ni < 4; ni++)
#pragma unroll
            for (int e = 0; e < 4; e++) acc[mi][ni][e] = 0.0f;

    auto load_tiles = [&](int buf, int kt) {
        const int k0 = kt * BK;
        float* Ab = As + buf * AS_F;
        float* Bb = Bs + buf * BS_F;
#pragma unroll
        for (int i = 0; i < 4; i++) {
            int lin = tid + i * 256;
            int r   = lin >> 3;
            int c4  = (lin & 7) * 4;
            cpa16(Ab + r * ALD + c4, A + (size_t)(bm + r) * K + k0 + c4);
        }
#pragma unroll
        for (int i = 0; i < 4; i++) {
            int lin = tid + i * 256;
            int r   = lin >> 3;
            int c4  = (lin & 7) * 4;
            cpa16(Bb + r * BLD + c4, Bt + (size_t)(bn + r) * K + k0 + c4);
        }
        cpa_commit();
    };

    const int nkt = K / BK;
    load_tiles(0, 0);
    load_tiles(1, 1);

    const int lrow = lane & 7;
    const int lbit = (lane >> 3) & 1;
    const int lco4 = (lane >> 4) * 4;
    const unsigned sA0 = (unsigned)__cvta_generic_to_shared(As);
    const unsigned sB0 = (unsigned)__cvta_generic_to_shared(Bs);
    const unsigned aoff = ((wr * 64 + lbit * 8 + lrow) * ALD + lco4) * 4;
    const unsigned boff = ((wc * 32 + lrow) * BLD + lbit * 4) * 4;

    for (int kt = 0; kt < nkt; kt++) {
        if (kt + 1 < nkt) cpa_wait<1>(); else cpa_wait<0>();
        __syncthreads();
        if (kt + 2 < nkt) load_tiles((kt + 2) % GST, kt + 2);

        const int buf = kt % GST;
        const unsigned abase = sA0 + buf * (AS_F * 4) + aoff;
        const unsigned bbase = sB0 + buf * (BS_F * 4) + boff;

#pragma unroll
        for (int j = 0; j < 4; j++) {
            unsigned bfr[4][2];
#pragma unroll
            for (int ni = 0; ni < 4; ni++)
                ldsm_x2(bfr[ni], bbase + (unsigned)(ni * 8 * BLD * 4 + j * 32));
#pragma unroll
            for (int mi = 0; mi < 4; mi++) {
                unsigned a[4];
                ldsm_x4(a, abase + (unsigned)(mi * 16 * ALD * 4 + j * 32));
#pragma unroll
                for (int ni = 0; ni < 4; ni++)
                    mma_tf32_16n8k8(acc[mi][ni], a, bfr[ni]);
            }
        }
    }

#pragma unroll
    for (int mi = 0; mi < 4; mi++) {
        const int gr0 = bm + wr * 64 + mi * 16 + g;
        const int gr1 = gr0 + 8;
#pragma unroll
        for (int ni = 0; ni < 4; ni++) {
            const int gc = bn + wc * 32 + ni * 8 + 2 * q;
            float d0 = acc[mi][ni][0], d1 = acc[mi][ni][1];
            float d2 = acc[mi][ni][2], d3 = acc[mi][ni][3];
            if (EPI == 3) {
                d0 = fmaxf(d0, 0.0f); d1 = fmaxf(d1, 0.0f);
                d2 = fmaxf(d2, 0.0f); d3 = fmaxf(d3, 0.0f);
            }
            if (EPI == 2) {
                int h = gc >> 6, d = gc & 63;
                int b0 = gr0 >> 11, l0i = gr0 & (cfg::Ls - 1);
                int b1 = gr1 >> 11, l1i = gr1 & (cfg::Ls - 1);
                float2 w0 = { f2tf_f(d0), f2tf_f(d1) };
                float2 w1 = { f2tf_f(d2), f2tf_f(d3) };
                *(float2*)&C[(((size_t)(b0 * cfg::Hh + h) * cfg::Ls + l0i) << 6) + d] = w0;
                *(float2*)&C[(((size_t)(b1 * cfg::Hh + h) * cfg::Ls + l1i) << 6) + d] = w1;
            } else if (EPI == 3) {
                float2 w0 = { f2tf_f(d0), f2tf_f(d1) };
                float2 w1 = { f2tf_f(d2), f2tf_f(d3) };
                *(float2*)&C[(size_t)gr0 * N + gc] = w0;
                *(float2*)&C[(size_t)gr1 * N + gc] = w1;
            } else {
                float2 w0 = { d0, d1 };
                float2 w1 = { d2, d3 };
                *(float2*)&C[(size_t)gr0 * N + gc] = w0;
                *(float2*)&C[(size_t)gr1 * N + gc] = w1;
            }
        }
    }
}

template <int EPI>
__global__ __launch_bounds__(256, 2) void gemm_tf32(
    const float* __restrict__ A, const float* __restrict__ Bt,
    float* __restrict__ C, int M, int N, int K)
{
    gemm_dev<EPI>(A, Bt, C, M, N, K);
}

__global__ __launch_bounds__(256, 2) void gemm_qkv(
    const float* __restrict__ q, const float* __restrict__ k,
    const float* __restrict__ v,
    const float* __restrict__ WQ, const float* __restrict__ WK,
    const float* __restrict__ WV,
    float* __restrict__ Qd, float* __restrict__ Kd, float* __restrict__ Vd)
{
    const int z = blockIdx.z;
    const float* A = (z == 0) ? q : (z == 1) ? k : v;
    const float* W = (z == 0) ? WQ : (z == 1) ? WK : WV;
    float* C       = (z == 0) ? Qd : (z == 1) ? Kd : Vd;
    gemm_dev<2>(A, W, C, cfg::Mtok, cfg::Din, cfg::Din);
}

// ---------------------------------------------------------------------------
// Flash attention v3: warp = 32 q-rows (2 m16 fragments), FQ = 256, 8 warps,
// 1 CTA/SM. Every K/V B-fragment read feeds TWO mma -> smem traffic per
// output row ~0.6x of v2 (the binding resource per R16 ncu: L1 = 59.8%).
// No mask prefetch (R16 regression reverted).
// ---------------------------------------------------------------------------
constexpr int FQ2  = 256;
constexpr int QSTR = 68;
constexpr int KSTR = 68;
constexpr int VSTR = 72;

constexpr int SM_Q = 0;                          // 256*68 = 17408 floats
constexpr int SM_K = SM_Q + FQ2 * QSTR;          // 2 * 64*68 = 8704
constexpr int SM_V = SM_K + 2 * 64 * KSTR;       // 2 * 64*72 = 9216
constexpr int FLASH2_FLOATS = SM_V + 2 * 64 * VSTR;            // 35328
constexpr size_t FLASH2_SMEM = (size_t)FLASH2_FLOATS * sizeof(float);  // 141,312 B

__global__ __launch_bounds__(256, 1) void flash3_kernel(
    const float* __restrict__ Qg, const float* __restrict__ Kg,
    const float* __restrict__ Vg, const float* __restrict__ maskg,
    float* __restrict__ Og)
{
    extern __shared__ float sm[];
    float* Qs = sm + SM_Q;
    float* Ks = sm + SM_K;
    float* Vs = sm + SM_V;

    const int tid  = threadIdx.x;
    const int warp = tid >> 5;
    const int lane = tid & 31;
    const int g    = lane >> 2;
    const int q    = lane & 3;
    const int b    = blockIdx.z;
    const int h    = blockIdx.y;
    const int q0   = blockIdx.x * FQ2;
    const int wrow = warp * 32;

    const size_t bh = (size_t)(b * cfg::Hh + h) * cfg::Ls;
    const float* Qbase = Qg + (bh + q0) * cfg::Dh;

    // Q: 256 rows x 16 float4 = 4096 chunks, 16 per thread
#pragma unroll
    for (int i = 0; i < 16; i++) {
        int lin = tid + i * 256;
        int r = lin >> 4, c4 = (lin & 15) * 4;
        cpa16(&Qs[r * QSTR + c4], Qbase + r * cfg::Dh + c4);
    }

    auto loadKV = [&](int buf, int kt) {
        const float* Kb = Kg + (bh + kt * 64) * cfg::Dh;
        const float* Vb = Vg + (bh + kt * 64) * cfg::Dh;
#pragma unroll
        for (int i = 0; i < 4; i++) {
            int lin = tid + i * 256;
            int r = lin >> 4, c4 = (lin & 15) * 4;
            cpa16(&Ks[buf * 64 * KSTR + r * KSTR + c4], Kb + r * cfg::Dh + c4);
            cpa16(&Vs[buf * 64 * VSTR + r * VSTR + c4], Vb + r * cfg::Dh + c4);
        }
    };
    loadKV(0, 0);
    cpa_commit();

    // Row-group state: half A = rows (wrow+g, wrow+g+8), half B = +16.
    float mA0 = -CUDART_INF_F, mA1 = -CUDART_INF_F;
    float mB0 = -CUDART_INF_F, mB1 = -CUDART_INF_F;
    float lA0 = 0.0f, lA1 = 0.0f, lB0 = 0.0f, lB1 = 0.0f;
    float o0[8][4], o1[8][4];
#pragma unroll
    for (int t = 0; t < 8; t++)
#pragma unroll
        for (int e = 0; e < 4; e++) { o0[t][e] = 0.0f; o1[t][e] = 0.0f; }

    const float* mr0 = maskg + ((size_t)b * cfg::Ls + q0 + wrow + g) * cfg::Ls;
    const float* mr1 = mr0 + 8  * (size_t)cfg::Ls;
    const float* mr2 = mr0 + 16 * (size_t)cfg::Ls;
    const float* mr3 = mr0 + 24 * (size_t)cfg::Ls;

    const unsigned* Qu = (const unsigned*)Qs;
    const int srcA = (lane & 28) | (q >> 1);
    const int srcB = srcA + 2;
    const bool odd = (q & 1) != 0;

    for (int kt = 0; kt < cfg::Ls / 64; kt++) {
        const int cur = kt & 1;
        cpa_wait<0>();
        __syncthreads();
        if (kt + 1 < cfg::Ls / 64) { loadKV(cur ^ 1, kt + 1); cpa_commit(); }

        const unsigned* Ku = (const unsigned*)(Ks + cur * 64 * KSTR);
        const unsigned* Vu = (const unsigned*)(Vs + cur * 64 * VSTR);

        // ---- S = Q K^T, two m16 fragments per warp sharing each B-frag ----
        float s0[8][4], s1[8][4];
#pragma unroll
        for (int t = 0; t < 8; t++)
#pragma unroll
            for (int e = 0; e < 4; e++) { s0[t][e] = 0.0f; s1[t][e] = 0.0f; }

#pragma unroll
        for (int j = 0; j < 8; j++) {
            unsigned a0[4], a1[4];
            a0[0] = Qu[(wrow + g) * QSTR + j * 8 + q];
            a0[1] = Qu[(wrow + g + 8) * QSTR + j * 8 + q];
            a0[2] = Qu[(wrow + g) * QSTR + j * 8 + q + 4];
            a0[3] = Qu[(wrow + g + 8) * QSTR + j * 8 + q + 4];
            a1[0] = Qu[(wrow + 16 + g) * QSTR + j * 8 + q];
            a1[1] = Qu[(wrow + 24 + g) * QSTR + j * 8 + q];
            a1[2] = Qu[(wrow + 16 + g) * QSTR + j * 8 + q + 4];
            a1[3] = Qu[(wrow + 24 + g) * QSTR + j * 8 + q + 4];
#pragma unroll
            for (int t = 0; t < 8; t++) {
                unsigned bf[2];
                bf[0] = Ku[(t * 8 + g) * KSTR + j * 8 + q];
                bf[1] = Ku[(t * 8 + g) * KSTR + j * 8 + q + 4];
                mma_tf32_16n8k8(s0[t], a0, bf);
                mma_tf32_16n8k8(s1[t], a1, bf);
            }
        }

        // ---- scale + mask ----
        const int kcol = kt * 64;
#pragma unroll
        for (int t = 0; t < 8; t++) {
            float2 k0 = *(const float2*)(mr0 + kcol + t * 8 + 2 * q);
            float2 k1 = *(const float2*)(mr1 + kcol + t * 8 + 2 * q);
            float2 k2 = *(const float2*)(mr2 + kcol + t * 8 + 2 * q);
            float2 k3 = *(const float2*)(mr3 + kcol + t * 8 + 2 * q);
            s0[t][0] = s0[t][0] * 0.125f + k0.x;
            s0[t][1] = s0[t][1] * 0.125f + k0.y;
            s0[t][2] = s0[t][2] * 0.125f + k1.x;
            s0[t][3] = s0[t][3] * 0.125f + k1.y;
            s1[t][0] = s1[t][0] * 0.125f + k2.x;
            s1[t][1] = s1[t][1] * 0.125f + k2.y;
            s1[t][2] = s1[t][2] * 0.125f + k3.x;
            s1[t][3] = s1[t][3] * 0.125f + k3.y;
        }

        // ---- online softmax (4 row-groups) ----
        float x0 = -CUDART_INF_F, x1 = -CUDART_INF_F;
        float x2 = -CUDART_INF_F, x3 = -CUDART_INF_F;
#pragma unroll
        for (int t = 0; t < 8; t++) {
            x0 = fmaxf(x0, fmaxf(s0[t][0], s0[t][1]));
            x1 = fmaxf(x1, fmaxf(s0[t][2], s0[t][3]));
            x2 = fmaxf(x2, fmaxf(s1[t][0], s1[t][1]));
            x3 = fmaxf(x3, fmaxf(s1[t][2], s1[t][3]));
        }
        x0 = fmaxf(x0, __shfl_xor_sync(0xffffffffu, x0, 1));
        x0 = fmaxf(x0, __shfl_xor_sync(0xffffffffu, x0, 2));
        x1 = fmaxf(x1, __shfl_xor_sync(0xffffffffu, x1, 1));
        x1 = fmaxf(x1, __shfl_xor_sync(0xffffffffu, x1, 2));
        x2 = fmaxf(x2, __shfl_xor_sync(0xffffffffu, x2, 1));
        x2 = fmaxf(x2, __shfl_xor_sync(0xffffffffu, x2, 2));
        x3 = fmaxf(x3, __shfl_xor_sync(0xffffffffu, x3, 1));
        x3 = fmaxf(x3, __shfl_xor_sync(0xffffffffu, x3, 2));

        const float nA0 = fmaxf(mA0, x0), nA1 = fmaxf(mA1, x1);
        const float nB0 = fmaxf(mB0, x2), nB1 = fmaxf(mB1, x3);
        const float cA0 = __expf(mA0 - nA0), cA1 = __expf(mA1 - nA1);
        const float cB0 = __expf(mB0 - nB0), cB1 = __expf(mB1 - nB1);

        float uA0 = 0.0f, uA1 = 0.0f, uB0 = 0.0f, uB1 = 0.0f;
#pragma unroll
        for (int t = 0; t < 8; t++) {
            s0[t][0] = __expf(s0[t][0] - nA0);
            s0[t][1] = __expf(s0[t][1] - nA0);
            s0[t][2] = __expf(s0[t][2] - nA1);
            s0[t][3] = __expf(s0[t][3] - nA1);
            s1[t][0] = __expf(s1[t][0] - nB0);
            s1[t][1] = __expf(s1[t][1] - nB0);
            s1[t][2] = __expf(s1[t][2] - nB1);
            s1[t][3] = __expf(s1[t][3] - nB1);
            uA0 += s0[t][0] + s0[t][1];
            uA1 += s0[t][2] + s0[t][3];
            uB0 += s1[t][0] + s1[t][1];
            uB1 += s1[t][2] + s1[t][3];
        }
        uA0 += __shfl_xor_sync(0xffffffffu, uA0, 1);
        uA0 += __shfl_xor_sync(0xffffffffu, uA0, 2);
        uA1 += __shfl_xor_sync(0xffffffffu, uA1, 1);
        uA1 += __shfl_xor_sync(0xffffffffu, uA1, 2);
        uB0 += __shfl_xor_sync(0xffffffffu, uB0, 1);
        uB0 += __shfl_xor_sync(0xffffffffu, uB0, 2);
        uB1 += __shfl_xor_sync(0xffffffffu, uB1, 1);
        uB1 += __shfl_xor_sync(0xffffffffu, uB1, 2);

        lA0 = lA0 * cA0 + uA0;  lA1 = lA1 * cA1 + uA1;
        lB0 = lB0 * cB0 + uB0;  lB1 = lB1 * cB1 + uB1;
        mA0 = nA0; mA1 = nA1; mB0 = nB0; mB1 = nB1;

#pragma unroll
        for (int t = 0; t < 8; t++) {
            o0[t][0] *= cA0; o0[t][1] *= cA0;
            o0[t][2] *= cA1; o0[t][3] *= cA1;
            o1[t][0] *= cB0; o1[t][1] *= cB0;
            o1[t][2] *= cB1; o1[t][3] *= cB1;
        }

        // ---- O += P V : V B-frags shared by both m16 fragments ----
#pragma unroll
        for (int j = 0; j < 8; j++) {
            float p0 = __shfl_sync(0xffffffffu, s0[j][0], srcA);
            float p1 = __shfl_sync(0xffffffffu, s0[j][1], srcA);
            float p2 = __shfl_sync(0xffffffffu, s0[j][0], srcB);
            float p3 = __shfl_sync(0xffffffffu, s0[j][1], srcB);
            float p4 = __shfl_sync(0xffffffffu, s0[j][2], srcA);
            float p5 = __shfl_sync(0xffffffffu, s0[j][3], srcA);
            float p6 = __shfl_sync(0xffffffffu, s0[j][2], srcB);
            float p7 = __shfl_sync(0xffffffffu, s0[j][3], srcB);
            unsigned aP0[4];
            aP0[0] = f2tf(odd ? p1 : p0);
            aP0[1] = f2tf(odd ? p5 : p4);
            aP0[2] = f2tf(odd ? p3 : p2);
            aP0[3] = f2tf(odd ? p7 : p6);

            float r0 = __shfl_sync(0xffffffffu, s1[j][0], srcA);
            float r1 = __shfl_sync(0xffffffffu, s1[j][1], srcA);
            float r2 = __shfl_sync(0xffffffffu, s1[j][0], srcB);
            float r3 = __shfl_sync(0xffffffffu, s1[j][1], srcB);
            float r4 = __shfl_sync(0xffffffffu, s1[j][2], srcA);
            float r5 = __shfl_sync(0xffffffffu, s1[j][3], srcA);
            float r6 = __shfl_sync(0xffffffffu, s1[j][2], srcB);
            float r7 = __shfl_sync(0xffffffffu, s1[j][3], srcB);
            unsigned aP1[4];
            aP1[0] = f2tf(odd ? r1 : r0);
            aP1[1] = f2tf(odd ? r5 : r4);
            aP1[2] = f2tf(odd ? r3 : r2);
            aP1[3] = f2tf(odd ? r7 : r6);

#pragma unroll
            for (int t = 0; t < 8; t++) {
                unsigned bf[2];
                bf[0] = Vu[(j * 8 + q) * VSTR + t * 8 + g];
                bf[1] = Vu[(j * 8 + q + 4) * VSTR + t * 8 + g];
                mma_tf32_16n8k8(o0[t], aP0, bf);
                mma_tf32_16n8k8(o1[t], aP1, bf);
            }
        }
    }

    // ---- normalize, tf32-truncate & write concat layout ----
    const float iA0 = 1.0f / lA0, iA1 = 1.0f / lA1;
    const float iB0 = 1.0f / lB0, iB1 = 1.0f / lB1;
    float* or0 = Og + ((size_t)b * cfg::Ls + q0 + wrow + g) * cfg::Din + h * cfg::Dh;
    float* or1 = or0 + 8  * (size_t)cfg::Din;
    float* or2 = or0 + 16 * (size_t)cfg::Din;
    float* or3 = or0 + 24 * (size_t)cfg::Din;
#pragma unroll
    for (int t = 0; t < 8; t++) {
        float2 w0 = { f2tf_f(o0[t][0] * iA0), f2tf_f(o0[t][1] * iA0) };
        float2 w1 = { f2tf_f(o0[t][2] * iA1), f2tf_f(o0[t][3] * iA1) };
        float2 w2 = { f2tf_f(o1[t][0] * iB0), f2tf_f(o1[t][1] * iB0) };
        float2 w3 = { f2tf_f(o1[t][2] * iB1), f2tf_f(o1[t][3] * iB1) };
        *(float2*)&or0[t * 8 + 2 * q] = w0;
        *(float2*)&or1[t * 8 + 2 * q] = w1;
        *(float2*)&or2[t * 8 + 2 * q] = w2;
        *(float2*)&or3[t * 8 + 2 * q] = w3;
    }
}

// ---------------------------------------------------------------------------
// Fused residual-add + LayerNorm over last dim (512). One block per row.
// ---------------------------------------------------------------------------
template <bool T32>
__global__ __launch_bounds__(128) void ln_add_kernel(
    const float* __restrict__ x, const float* __restrict__ y,
    float* __restrict__ out, float* __restrict__ out_t)
{
    const int row = blockIdx.x;
    const float* px = x + (size_t)row * cfg::Din;
    const float* py = y + (size_t)row * cfg::Din;

    float v[4];
    float s = 0.0f, sq = 0.0f;
#pragma unroll
    for (int i = 0; i < 4; i++) {
        int c = threadIdx.x + i * 128;
        v[i] = px[c] + py[c];
        s  += v[i];
        sq += v[i] * v[i];
    }
#pragma unroll
    for (int o = 16; o > 0; o >>= 1) {
        s  += __shfl_xor_sync(0xffffffffu, s, o);
        sq += __shfl_xor_sync(0xffffffffu, sq, o);
    }
    __shared__ float ws[4], wq[4];
    __shared__ float mean_s, inv_s;
    const int warp = threadIdx.x >> 5, lane = threadIdx.x & 31;
    if (lane == 0) { ws[warp] = s; wq[warp] = sq; }
    __syncthreads();
    if (threadIdx.x == 0) {
        float S = ws[0] + ws[1] + ws[2] + ws[3];
        float Q = wq[0] + wq[1] + wq[2] + wq[3];
        float mean = S * (1.0f / cfg::Din);
        float var  = Q * (1.0f / cfg::Din) - mean * mean;
        mean_s = mean;
        inv_s  = rsqrtf(var + 1e-5f);
    }
    __syncthreads();
    float* po = out + (size_t)row * cfg::Din;
    float* pt = out_t + (size_t)row * cfg::Din;
#pragma unroll
    for (int i = 0; i < 4; i++) {
        int c = threadIdx.x + i * 128;
        float r = (v[i] - mean_s) * inv_s;
        po[c] = r;
        if (T32) pt[c] = f2tf_f(r);
    }
}

// ---------------------------------------------------------------------------
// kernel_launch
// ---------------------------------------------------------------------------
extern "C" void kernel_launch(void* const* d_in, const int* in_sizes, int n_in,
                              void* d_out, int out_size)
{
    const float* query = (const float*)d_in[0];
    const float* key   = (const float*)d_in[1];
    const float* value = (const float*)d_in[2];
    const float* mask  = (const float*)d_in[3];
    const float* WQ    = (const float*)d_in[4];
    const float* WK    = (const float*)d_in[5];
    const float* WV    = (const float*)d_in[6];
    const float* WO    = (const float*)d_in[7];
    const float* W1    = (const float*)d_in[8];
    const float* W2    = (const float*)d_in[9];
    float* out = (float*)d_out;

    float *Qd, *Kd, *Vd, *attn, *proj, *h1, *h1t, *mid, *ff;
    float *qt, *kt, *vt, *WQt, *WKt, *WVt, *WOt, *W1t, *W2t;
    cudaGetSymbolAddress((void**)&Qd,   g_Q);
    cudaGetSymbolAddress((void**)&Kd,   g_K);
    cudaGetSymbolAddress((void**)&Vd,   g_V);
    cudaGetSymbolAddress((void**)&attn, g_attn);
    cudaGetSymbolAddress((void**)&proj, g_proj);
    cudaGetSymbolAddress((void**)&h1,   g_h1);
    cudaGetSymbolAddress((void**)&h1t,  g_h1t);
    cudaGetSymbolAddress((void**)&mid,  g_mid);
    cudaGetSymbolAddress((void**)&ff,   g_ff);
    cudaGetSymbolAddress((void**)&qt,   g_qt);
    cudaGetSymbolAddress((void**)&kt,   g_kt);
    cudaGetSymbolAddress((void**)&vt,   g_vt);
    cudaGetSymbolAddress((void**)&WQt,  g_WQt);
    cudaGetSymbolAddress((void**)&WKt,  g_WKt);
    cudaGetSymbolAddress((void**)&WVt,  g_WVt);
    cudaGetSymbolAddress((void**)&WOt,  g_WOt);
    cudaGetSymbolAddress((void**)&W1t,  g_W1t);
    cudaGetSymbolAddress((void**)&W2t,  g_W2t);

    cudaFuncSetAttribute(flash3_kernel, cudaFuncAttributeMaxDynamicSharedMemorySize,
                         (int)FLASH2_SMEM);
    cudaFuncSetAttribute(gemm_tf32<0>, cudaFuncAttributeMaxDynamicSharedMemorySize,
                         (int)GEMM_SMEM);
    cudaFuncSetAttribute(gemm_tf32<3>, cudaFuncAttributeMaxDynamicSharedMemorySize,
                         (int)GEMM_SMEM);
    cudaFuncSetAttribute(gemm_qkv, cudaFuncAttributeMaxDynamicSharedMemorySize,
                         (int)GEMM_SMEM);

    // -- prologue: tf32 cvt of q/k/v + ONE batched transpose+cvt launch --
    const int nIn = cfg::Mtok * cfg::Din;
    Cvt3 cv;
    cv.s[0] = query; cv.d[0] = qt; cv.n[0] = nIn;
    cv.s[1] = key;   cv.d[1] = kt; cv.n[1] = nIn;
    cv.s[2] = value; cv.d[2] = vt; cv.n[2] = nIn;
    cvt3_kernel<<<1024, 256>>>(cv);

    T6 tj;
    const float* Ws[6] = { WQ, WK, WV, WO, W1, W2 };
    float* Wts[6]      = { WQt, WKt, WVt, WOt, W1t, W2t };
    const int Ks[6]    = { 512, 512, 512, 512, 512, 2048 };
    const int Ns[6]    = { 512, 512, 512, 512, 2048, 512 };
    int acc_t = 0;
    for (int i = 0; i < 6; i++) {
        tj.W[i] = Ws[i]; tj.Wt[i] = Wts[i]; tj.K[i] = Ks[i]; tj.N[i] = Ns[i];
        tj.tstart[i] = acc_t;
        acc_t += (Ks[i] / 32) * (Ns[i] / 32);
    }
    tj.tstart[6] = acc_t;                       // 3072
    transpose6_kernel<<<acc_t, 256>>>(tj);

    const dim3 gProj(cfg::Din / BN, cfg::Mtok / BM);        // (4, 64)
    const dim3 gQkv (cfg::Din / BN, cfg::Mtok / BM, 3);     // (4, 64, 3)
    const dim3 gFfn1(cfg::Dmid / BN, cfg::Mtok / BM);       // (16, 64)

    // Fused QKV projections (head-split + tf32 epilogue)
    gemm_qkv<<<gQkv, 256, GEMM_SMEM>>>(qt, kt, vt, WQt, WKt, WVt, Qd, Kd, Vd);

    // Flash attention (consumes tf32 Q/K/V, emits tf32 attn)
    dim3 gFlash(cfg::Ls / FQ2, cfg::Hh, cfg::Bb);           // (8, 8, 4)
    flash3_kernel<<<gFlash, 256, FLASH2_SMEM>>>(Qd, Kd, Vd, mask, attn);

    // Output projection + residual LN (fp32 out + tf32 copy for FFN1)
    gemm_tf32<0><<<gProj, 256, GEMM_SMEM>>>(attn, WOt, proj, cfg::Mtok, cfg::Din, cfg::Din);
    ln_add_kernel<true><<<cfg::Mtok, 128>>>(query, proj, h1, h1t);

    // FFN (FFN1: relu + tf32 epilogue; FFN2: fp32)
    gemm_tf32<3><<<gFfn1, 256, GEMM_SMEM>>>(h1t, W1t, mid, cfg::Mtok, cfg::Dmid, cfg::Din);
    gemm_tf32<0><<<gProj, 256, GEMM_SMEM>>>(mid, W2t, ff, cfg::Mtok, cfg::Din, cfg::Dmid);
    ln_add_kernel<false><<<cfg::Mtok, 128>>>(h1, ff, out, out);

    (void)in_sizes; (void)n_in; (void)out_size;
}